// round 13
// baseline (speedup 1.0000x reference)
#include <cuda_runtime.h>
#include <cstdint>
#include <float.h>
#include <math.h>

// Problem constants (fixed by the dataset)
#define TT 64
#define UU 142
#define II 4500
#define BB 16384
#define KK 10

#define NPER 5                 // interleaved: lane owns users v = lane + 32*j
#define FULL_MASK 0xFFFFFFFFu
#define NWARPS 8192            // 2 rows per warp

// Candidate threshold: sims ~ 0.5(s+s^T), triangular(-1,1).
// P(sim>0.35)~0.21 -> ~30 candidates, ~21 rated; P(<10 rated) small -> fallback.
#define THETA 0.35f

// order-preserving float->uint map; 0 reserved as invalid/consumed sentinel
// (all real keys >= f2ord(0.0f) = 0x80000000 > 0)
__device__ __forceinline__ unsigned f2ord(float f) {
    unsigned b = __float_as_uint(f);
    return (b & 0x80000000u) ? ~b : (b | 0x80000000u);
}
__device__ __forceinline__ float ord2f(unsigned o) {
    return __uint_as_float((o & 0x80000000u) ? (o ^ 0x80000000u) : ~o);
}
__device__ __forceinline__ unsigned umax5(const unsigned o[NPER]) {
    unsigned a = max(o[0], o[1]);
    unsigned b = max(o[2], o[3]);
    return max(max(a, b), o[4]);
}

__global__ __launch_bounds__(128, 11)
void ucf_kernel(const float* __restrict__ qos,      // (T,U,I)
                const float* __restrict__ uavg,     // (T,U)
                const float* __restrict__ sim,      // (U,U)
                const int*   __restrict__ user_id,  // (B,)
                const int*   __restrict__ item_id,  // (B,)
                const int*   __restrict__ time_id,  // (B,)
                float*       __restrict__ out)      // (B,)
{
    const int gwarp = (blockIdx.x * blockDim.x + threadIdx.x) >> 5;
    const int lane  = threadIdx.x & 31;

    const int rA = gwarp;
    const int rB = gwarp + NWARPS;

    const int uA = __ldg(user_id + rA), iA = __ldg(item_id + rA), tA = __ldg(time_id + rA);
    const int uB = __ldg(user_id + rB), iB = __ldg(item_id + rB), tB = __ldg(time_id + rB);

    const float* __restrict__ qbA = qos + (size_t)tA * (UU * II) + iA;
    const float* __restrict__ qbB = qos + (size_t)tB * (UU * II) + iB;
    const float* __restrict__ srA = sim + (size_t)uA * UU;
    const float* __restrict__ srB = sim + (size_t)uB * UU;
    const float* __restrict__ avA = uavg + (size_t)tA * UU;
    const float* __restrict__ avB = uavg + (size_t)tB * UU;

    // 1) sim rows, both rows interleaved (coalesced 128B per LDG, L2-resident)
    float svA[NPER], svB[NPER];
    #pragma unroll
    for (int j = 0; j < NPER; j++) {
        const int v = lane + 32 * j;
        const bool ok = (v < UU);
        svA[j] = ok ? __ldg(srA + v) : 0.0f;
        svB[j] = ok ? __ldg(srB + v) : 0.0f;
    }

    // 2) candidate masks; probe qos ONLY for candidates (both rows in flight)
    unsigned candA = 0, candB = 0;
    #pragma unroll
    for (int j = 0; j < NPER; j++) {
        const int v = lane + 32 * j;
        if (v < UU && svA[j] > THETA) candA |= 1u << j;
        if (v < UU && svB[j] > THETA) candB |= 1u << j;
    }
    float qvA[NPER], qvB[NPER];
    #pragma unroll
    for (int j = 0; j < NPER; j++) {
        const int v = lane + 32 * j;
        qvA[j] = ((candA >> j) & 1u) ? __ldg(qbA + (size_t)v * II) : 0.0f;
        qvB[j] = ((candB >> j) & 1u) ? __ldg(qbB + (size_t)v * II) : 0.0f;
    }

    // 3) rated-candidate counts, both rows in ONE reduce (byte-packed popc)
    unsigned ratedA = 0, ratedB = 0;
    #pragma unroll
    for (int j = 0; j < NPER; j++) {
        if (((candA >> j) & 1u) && qvA[j] > 0.0f) ratedA |= 1u << j;
        if (((candB >> j) & 1u) && qvB[j] > 0.0f) ratedB |= 1u << j;
    }
    const int packed = __popc(ratedA) | (__popc(ratedB) << 8);  // sums <= 160 per byte
    const int cnts   = __reduce_add_sync(FULL_MASK, packed);
    const int cntA = cnts & 0xFF, cntB = cnts >> 8;

    // 4) keys (fast path: rated candidates only; rare exact full fallback)
    unsigned ordA[NPER], ordB[NPER];
    if (cntA >= KK) {
        #pragma unroll
        for (int j = 0; j < NPER; j++)
            ordA[j] = ((ratedA >> j) & 1u) ? f2ord(svA[j]) : 0u;
    } else {
        #pragma unroll
        for (int j = 0; j < NPER; j++) {
            const int v = lane + 32 * j;
            qvA[j] = (v < UU) ? __ldg(qbA + (size_t)v * II) : 0.0f;
        }
        #pragma unroll
        for (int j = 0; j < NPER; j++) {
            const int v = lane + 32 * j;
            ordA[j] = (v < UU) ? f2ord(qvA[j] > 0.0f ? svA[j] : 0.0f) : 0u;
        }
    }
    if (cntB >= KK) {
        #pragma unroll
        for (int j = 0; j < NPER; j++)
            ordB[j] = ((ratedB >> j) & 1u) ? f2ord(svB[j]) : 0u;
    } else {
        #pragma unroll
        for (int j = 0; j < NPER; j++) {
            const int v = lane + 32 * j;
            qvB[j] = (v < UU) ? __ldg(qbB + (size_t)v * II) : 0.0f;
        }
        #pragma unroll
        for (int j = 0; j < NPER; j++) {
            const int v = lane + 32 * j;
            ordB[j] = (v < UU) ? f2ord(qvB[j] > 0.0f ? svB[j] : 0.0f) : 0u;
        }
    }

    // 5) two interleaved top-K loops: 4xUMAX local max, one REDUX.MAX + ballot
    //    per row per iteration; winner folds its contribution in immediately.
    float SA = 0.0f, SB = 0.0f, accA = 0.0f, accB = 0.0f;
    #pragma unroll
    for (int k = 0; k < KK; k++) {
        const unsigned bA = umax5(ordA);
        const unsigned bB = umax5(ordB);
        const unsigned mA = __reduce_max_sync(FULL_MASK, bA);
        const unsigned mB = __reduce_max_sync(FULL_MASK, bB);
        const unsigned wA = __ballot_sync(FULL_MASK, bA == mA);
        const unsigned wB = __ballot_sync(FULL_MASK, bB == mB);
        const float sA = ord2f(mA);
        const float sB = ord2f(mB);
        SA += sA; SB += sB;
        if (lane == __ffs(wA) - 1) {
            const int j = (ordA[0] == mA) ? 0 : (ordA[1] == mA) ? 1 :
                          (ordA[2] == mA) ? 2 : (ordA[3] == mA) ? 3 : 4;
            const float r = (j == 0) ? qvA[0] : (j == 1) ? qvA[1] :
                            (j == 2) ? qvA[2] : (j == 3) ? qvA[3] : qvA[4];
            if      (j == 0) ordA[0] = 0u;
            else if (j == 1) ordA[1] = 0u;
            else if (j == 2) ordA[2] = 0u;
            else if (j == 3) ordA[3] = 0u;
            else             ordA[4] = 0u;
            accA += sA * (r - __ldg(avA + lane + 32 * j));
        }
        if (lane == __ffs(wB) - 1) {
            const int j = (ordB[0] == mB) ? 0 : (ordB[1] == mB) ? 1 :
                          (ordB[2] == mB) ? 2 : (ordB[3] == mB) ? 3 : 4;
            const float r = (j == 0) ? qvB[0] : (j == 1) ? qvB[1] :
                            (j == 2) ? qvB[2] : (j == 3) ? qvB[3] : qvB[4];
            if      (j == 0) ordB[0] = 0u;
            else if (j == 1) ordB[1] = 0u;
            else if (j == 2) ordB[2] = 0u;
            else if (j == 3) ordB[3] = 0u;
            else             ordB[4] = 0u;
            accB += sB * (r - __ldg(avB + lane + 32 * j));
        }
    }

    // 6) reduce winner contributions; pred = avg_u + acc/denom
    #pragma unroll
    for (int off = 16; off > 0; off >>= 1) {
        accA += __shfl_xor_sync(FULL_MASK, accA, off);
        accB += __shfl_xor_sync(FULL_MASK, accB, off);
    }
    if (lane == 0) {
        out[rA] = __ldg(avA + uA) + accA / (SA + 1e-8f);
        out[rB] = __ldg(avB + uB) + accB / (SB + 1e-8f);
    }
}

extern "C" void kernel_launch(void* const* d_in, const int* in_sizes, int n_in,
                              void* d_out, int out_size)
{
    const float* qos   = (const float*)d_in[0];  // (64,142,4500)
    const float* uavg  = (const float*)d_in[1];  // (64,142)
    const float* sim   = (const float*)d_in[2];  // (142,142)
    const int*   uid   = (const int*)  d_in[3];  // (16384,)
    const int*   iid   = (const int*)  d_in[4];  // (16384,)
    const int*   tid   = (const int*)  d_in[5];  // (16384,)
    float*       out   = (float*)d_out;          // (16384,)

    const int threads = 128;                        // 4 warps/block
    const int blocks  = (NWARPS * 32) / threads;    // 2048
    ucf_kernel<<<blocks, threads>>>(qos, uavg, sim, uid, iid, tid, out);
}

// round 15
// speedup vs baseline: 1.4116x; 1.4116x over previous
#include <cuda_runtime.h>
#include <cstdint>
#include <float.h>
#include <math.h>

// Problem constants (fixed by the dataset)
#define TT 64
#define UU 142
#define II 4500
#define BB 16384
#define KK 10

#define NPER 5                 // interleaved: lane owns users v = lane + 32*j
#define FULL_MASK 0xFFFFFFFFu

// Candidate threshold: sims ~ 0.5(s+s^T), triangular(-1,1).
// P(sim>0.35)~0.21 -> ~30 candidates, ~21 rated; P(<10 rated) -> exact fallback.
#define THETA 0.35f

// order-preserving float->uint map; 0 reserved as invalid/consumed sentinel
// (all real keys >= f2ord(0.0f) = 0x80000000 > 0)
__device__ __forceinline__ unsigned f2ord(float f) {
    unsigned b = __float_as_uint(f);
    return (b & 0x80000000u) ? ~b : (b | 0x80000000u);
}
__device__ __forceinline__ float ord2f(unsigned o) {
    return __uint_as_float((o & 0x80000000u) ? (o ^ 0x80000000u) : ~o);
}
__device__ __forceinline__ unsigned umax5(const unsigned o[NPER]) {
    unsigned a = max(o[0], o[1]);
    unsigned b = max(o[2], o[3]);
    return max(max(a, b), o[4]);
}

__global__ __launch_bounds__(256)
void ucf_kernel(const float* __restrict__ qos,      // (T,U,I)
                const float* __restrict__ uavg,     // (T,U)
                const float* __restrict__ sim,      // (U,U)
                const int*   __restrict__ user_id,  // (B,)
                const int*   __restrict__ item_id,  // (B,)
                const int*   __restrict__ time_id,  // (B,)
                float*       __restrict__ out)      // (B,)
{
    const int warp = (blockIdx.x * blockDim.x + threadIdx.x) >> 5;
    const int lane = threadIdx.x & 31;
    if (warp >= BB) return;

    const int u = __ldg(user_id + warp);
    const int i = __ldg(item_id + warp);
    const int t = __ldg(time_id + warp);

    const float* __restrict__ qbase = qos + (size_t)t * (UU * II) + i;
    const float* __restrict__ srow  = sim + (size_t)u * UU;
    const float* __restrict__ arow  = uavg + (size_t)t * UU;

    // 1) sim row (coalesced 128B LDGs, L2-resident)
    float sv[NPER];
    #pragma unroll
    for (int j = 0; j < NPER; j++) {
        const int v = lane + 32 * j;
        sv[j] = (v < UU) ? __ldg(srow + v) : 0.0f;
    }

    // 2) candidates: sim > THETA; probe qos ONLY for candidates
    unsigned candmask = 0;
    #pragma unroll
    for (int j = 0; j < NPER; j++) {
        const int v = lane + 32 * j;
        if (v < UU && sv[j] > THETA) candmask |= 1u << j;
    }
    float qv[NPER];
    #pragma unroll
    for (int j = 0; j < NPER; j++) {
        const int v = lane + 32 * j;
        qv[j] = ((candmask >> j) & 1u) ? __ldg(qbase + (size_t)v * II) : 0.0f;
    }

    // 3) count rated candidates (one popc + one add-reduce)
    unsigned ratedmask = 0;
    #pragma unroll
    for (int j = 0; j < NPER; j++)
        if (((candmask >> j) & 1u) && qv[j] > 0.0f) ratedmask |= 1u << j;
    const int cnt = __reduce_add_sync(FULL_MASK, __popc(ratedmask));

    // 4) keys: fast path if top-10 provably among rated candidates
    unsigned ordu[NPER];
    if (cnt >= KK) {
        #pragma unroll
        for (int j = 0; j < NPER; j++)
            ordu[j] = ((ratedmask >> j) & 1u) ? f2ord(sv[j]) : 0u;
    } else {
        // rare exact fallback: full masked top-K over all 142
        #pragma unroll
        for (int j = 0; j < NPER; j++) {
            const int v = lane + 32 * j;
            qv[j] = (v < UU) ? __ldg(qbase + (size_t)v * II) : 0.0f;
        }
        #pragma unroll
        for (int j = 0; j < NPER; j++) {
            const int v = lane + 32 * j;
            ordu[j] = (v < UU) ? f2ord(qv[j] > 0.0f ? sv[j] : 0.0f) : 0u;
        }
    }

    // 5) top-K: umax5 local scan, ONE REDUX.MAX + ballot per iteration.
    //    Winner (lowest lane holding max) recovers j by equality chain,
    //    zeroes its key, records selection. Selection-set identical to the
    //    exact rule except for exact cross-lane key ties (zero-measure or
    //    zero-contribution). S accumulated uniformly from the broadcast max.
    unsigned selmask = 0;
    float S = 0.0f;
    #pragma unroll
    for (int k = 0; k < KK; k++) {
        const unsigned best   = umax5(ordu);
        const unsigned maxord = __reduce_max_sync(FULL_MASK, best);
        const unsigned winners = __ballot_sync(FULL_MASK, best == maxord);
        S += ord2f(maxord);                        // k-th largest, all lanes
        if (lane == __ffs(winners) - 1) {
            const int j = (ordu[0] == maxord) ? 0 : (ordu[1] == maxord) ? 1 :
                          (ordu[2] == maxord) ? 2 : (ordu[3] == maxord) ? 3 : 4;
            if      (j == 0) ordu[0] = 0u;
            else if (j == 1) ordu[1] = 0u;
            else if (j == 2) ordu[2] = 0u;
            else if (j == 3) ordu[3] = 0u;
            else             ordu[4] = 0u;
            selmask |= 1u << j;
        }
    }

    // 6) epilogue: acc = sum_k s_k*(r_k - avg_k); loads issue together (MLP),
    //    OUTSIDE any serial chain; single divide at the end.
    float acc = 0.0f;
    #pragma unroll
    for (int j = 0; j < NPER; j++) {
        if ((selmask >> j) & 1u) {
            const int v = lane + 32 * j;
            const float s = (qv[j] > 0.0f) ? sv[j] : 0.0f;  // masked weight
            acc += s * (qv[j] - __ldg(arow + v));
        }
    }
    #pragma unroll
    for (int off = 16; off > 0; off >>= 1)
        acc += __shfl_xor_sync(FULL_MASK, acc, off);

    if (lane == 0)
        out[warp] = __ldg(arow + u) + acc / (S + 1e-8f);
}

extern "C" void kernel_launch(void* const* d_in, const int* in_sizes, int n_in,
                              void* d_out, int out_size)
{
    const float* qos   = (const float*)d_in[0];  // (64,142,4500)
    const float* uavg  = (const float*)d_in[1];  // (64,142)
    const float* sim   = (const float*)d_in[2];  // (142,142)
    const int*   uid   = (const int*)  d_in[3];  // (16384,)
    const int*   iid   = (const int*)  d_in[4];  // (16384,)
    const int*   tid   = (const int*)  d_in[5];  // (16384,)
    float*       out   = (float*)d_out;          // (16384,)

    const int threads = 256;                 // R9-verified shape: 1 row/warp
    const int blocks  = (BB * 32) / threads; // 2048
    ucf_kernel<<<blocks, threads>>>(qos, uavg, sim, uid, iid, tid, out);
}